// round 13
// baseline (speedup 1.0000x reference)
#include <cuda_runtime.h>
#include <cstdint>

#define NA  32768
#define MM  32
#define AIN 92
#define FF  64
#define NBH 8
#define HH  128
#define ODD 16

// ---------------- scratch (static device globals; no allocation) ----------------
__device__ float g_atom [NA*FF];
__device__ float g_nbrh [NA*MM*NBH];
__device__ float g_mask [NA*MM];
__device__ float g_phic [NA*FF];
__device__ float g_phin [NA*FF];
__device__ float g_h1   [NA*HH];
__device__ float g_pi   [NA*ODD];
__device__ float g_pj   [NA*ODD];
__device__ float g_esite[NA];

// ---------------- helpers ----------------
__device__ __forceinline__ float wsum(float v) {
#pragma unroll
    for (int o = 16; o; o >>= 1) v += __shfl_xor_sync(0xffffffffu, v, o);
    return v;
}
__device__ __forceinline__ float sigm(float x) {
    return __fdividef(1.0f, 1.0f + __expf(-x));
}
__device__ __forceinline__ float sftp(float x) {
    return (x > 15.0f) ? x : __logf(1.0f + __expf(x));
}
__device__ __forceinline__ uint32_t to_tf32(float x) {
    uint32_t r;
    asm("cvt.rna.tf32.f32 %0, %1;" : "=r"(r) : "f"(x));
    return r;
}
// m16n8k8 tf32 mma, fp32 accumulate (sm_80+ PTX; compiles under compute_100)
__device__ __forceinline__ void mma8(float* c, const uint32_t* a, const uint32_t* b) {
    asm volatile("mma.sync.aligned.m16n8k8.row.col.f32.tf32.tf32.f32 "
        "{%0,%1,%2,%3}, {%4,%5,%6,%7}, {%8,%9}, {%0,%1,%2,%3};"
        : "+f"(c[0]), "+f"(c[1]), "+f"(c[2]), "+f"(c[3])
        : "r"(a[0]), "r"(a[1]), "r"(a[2]), "r"(a[3]), "r"(b[0]), "r"(b[1]));
}

// SMEM float offsets for k_conv
#define KC_SA   68              // A row stride (floats): conflict-free fragment reads
#define KC_SB   136             // B row stride (floats)
#define KC_AOF  0               // A: 128*68 = 8704 floats
#define KC_BOF  8704            // B: 64*136 = 8704 floats
#define KC_WE   17408           // 512
#define KC_BE   17920           // 64
#define KC_BG   17984           // 64
#define KC_BM   18048           // 64
#define KC_PC   18112           // 256
#define KC_FLOATS 18368         // 73472 bytes

// ---------------- 1) embed ----------------
__global__ void k_embed(const float* __restrict__ atom_fea,
                        const float* __restrict__ W, const float* __restrict__ b) {
    __shared__ float Ws[AIN*FF];
    __shared__ float bs[FF];
    __shared__ float xb[8][AIN + 1];
    int tid = threadIdx.x;
    for (int i = tid; i < AIN*FF; i += 256) Ws[i] = W[i];
    if (tid < FF) bs[tid] = b[tid];
    int w = tid >> 5, l = tid & 31;
    int i = blockIdx.x * 8 + w;
    for (int k = l; k < AIN; k += 32) xb[w][k] = atom_fea[i*AIN + k];
    __syncthreads();
    float a0 = bs[l], a1 = bs[l+32];
#pragma unroll 4
    for (int k = 0; k < AIN; k++) {
        float x = xb[w][k];
        a0 = fmaf(x, Ws[k*FF + l],      a0);
        a1 = fmaf(x, Ws[k*FF + l + 32], a1);
    }
    g_atom[i*FF + l]      = a0;
    g_atom[i*FF + l + 32] = a1;
}

// ---------------- 2) nbr_h + mask ----------------
__global__ void k_nbrh(const float4* __restrict__ nbr_fea4,
                       const float* __restrict__ W, const float* __restrict__ b) {
    __shared__ float Ws[64];
    __shared__ float bs[8];
    int tid = threadIdx.x;
    if (tid < 64) Ws[tid] = W[tid];
    if (tid < 8)  bs[tid] = b[tid];
    __syncthreads();
    int p = blockIdx.x * 256 + tid;
    float4 x0 = nbr_fea4[p*2], x1 = nbr_fea4[p*2 + 1];
    float x[8] = {x0.x, x0.y, x0.z, x0.w, x1.x, x1.y, x1.z, x1.w};
    float mk = 0.0f;
#pragma unroll
    for (int h = 0; h < 8; h++) if (x[h] > 0.0f) mk = 1.0f;
    float o[8];
#pragma unroll
    for (int c = 0; c < 8; c++) {
        float acc = bs[c];
#pragma unroll
        for (int h = 0; h < 8; h++) acc = fmaf(x[h], Ws[h*8 + c], acc);
        o[c] = acc;
    }
    float4* out4 = (float4*)(g_nbrh + p*8);
    out4[0] = make_float4(o[0], o[1], o[2], o[3]);
    out4[1] = make_float4(o[4], o[5], o[6], o[7]);
    g_mask[p] = mk;
}

// ---------------- 3) LN + phi_c/phi_n ----------------
__global__ void k_lnphi(const float* __restrict__ ln_s, const float* __restrict__ ln_b,
                        const float* __restrict__ Wc, const float* __restrict__ bc,
                        const float* __restrict__ Wn, const float* __restrict__ bn) {
    __shared__ float Wcs[FF*FF];
    __shared__ float Wns[FF*FF];
    __shared__ float bcs[FF], bns[FF], lss[FF], lbs[FF];
    __shared__ float nb[8][FF];
    int tid = threadIdx.x;
    for (int i = tid; i < FF*FF; i += 256) { Wcs[i] = Wc[i]; Wns[i] = Wn[i]; }
    if (tid < FF) { bcs[tid] = bc[tid]; bns[tid] = bn[tid]; lss[tid] = ln_s[tid]; lbs[tid] = ln_b[tid]; }
    int w = tid >> 5, l = tid & 31;
    int i = blockIdx.x * 8 + w;
    float x0 = g_atom[i*FF + l], x1 = g_atom[i*FF + l + 32];
    float mu = wsum(x0 + x1) * (1.0f / 64.0f);
    float d0 = x0 - mu, d1 = x1 - mu;
    float var = wsum(d0*d0 + d1*d1) * (1.0f / 64.0f);
    float rstd = rsqrtf(var + 1e-6f);
    __syncthreads();
    nb[w][l]      = fmaf(d0 * rstd, lss[l],      lbs[l]);
    nb[w][l + 32] = fmaf(d1 * rstd, lss[l + 32], lbs[l + 32]);
    __syncwarp();
    float c0 = bcs[l], c1 = bcs[l+32], n0 = bns[l], n1 = bns[l+32];
#pragma unroll 4
    for (int k = 0; k < FF; k++) {
        float nv = nb[w][k];
        c0 = fmaf(nv, Wcs[k*FF + l],      c0);
        c1 = fmaf(nv, Wcs[k*FF + l + 32], c1);
        n0 = fmaf(nv, Wns[k*FF + l],      n0);
        n1 = fmaf(nv, Wns[k*FF + l + 32], n1);
    }
    g_phic[i*FF + l] = c0;  g_phic[i*FF + l + 32] = c1;
    g_phin[i*FF + l] = n0;  g_phin[i*FF + l + 32] = n1;
}

// ---------------- 4) fused conv: mma.sync tf32, 512 threads ----------------
// block = 4 atoms = 128 pairs. D[128p x 128c] = A[128p x 64k] @ B[64k x 128c]
// cols 0..63 = gate (Wg), 64..127 = mag (Wm).
// 16 warps: warp w -> atom = w>>2 (rows atom*32..+31), col-quarter g = w&3
// (gate cols g*16..+15 paired with mag cols +64). 32 accumulators/thread.
__global__ void __launch_bounds__(512, 2)
k_conv(const float* __restrict__ Wg, const float* __restrict__ bg,
       const float* __restrict__ Wm, const float* __restrict__ bm,
       const float* __restrict__ We, const float* __restrict__ be,
       const int* __restrict__ nbr_idx) {
    extern __shared__ float sm[];
    float* As  = sm + KC_AOF;
    float* Bs  = sm + KC_BOF;
    float* WEs = sm + KC_WE;
    float* BEs = sm + KC_BE;
    float* BGs = sm + KC_BG;
    float* BMs = sm + KC_BM;
    float* PCs = sm + KC_PC;

    int tid = threadIdx.x, bi = blockIdx.x;

    // stage B[k][n] (tf32), biases, We, phi_c
    for (int i = tid; i < 8192; i += 512) {
        int k = i >> 7, n = i & 127;
        float w = (n < 64) ? Wg[k*64 + n] : Wm[k*64 + (n - 64)];
        ((uint32_t*)Bs)[k*KC_SB + n] = to_tf32(w);
    }
    if (tid < 512) WEs[tid] = We[tid];
    if (tid < 64) { BEs[tid] = be[tid]; BGs[tid] = bg[tid]; BMs[tid] = bm[tid]; }
    if (tid < 256) PCs[tid] = g_phic[bi*256 + tid];
    __syncthreads();

    // build A = inter (pair p = tid&127, k-quarter = tid>>7), tf32, stride 68
    {
        int p = tid & 127, quarter = tid >> 7, a = p >> 5;
        int gp = bi*128 + p;
        int nidx = nbr_idx[gp];
        const float4* h4 = (const float4*)(g_nbrh + gp*8);
        float4 hA = h4[0], hB = h4[1];
        float h8[8] = {hA.x, hA.y, hA.z, hA.w, hB.x, hB.y, hB.z, hB.w};
        int k0 = quarter * 16;
        const float4* pn4 = (const float4*)(g_phin + nidx*64 + k0);
        const float* pc  = PCs + a*64 + k0;
        const float* beL = BEs + k0;
#pragma unroll
        for (int q = 0; q < 4; q++) {
            float4 pnv = pn4[q];
            float pn[4] = {pnv.x, pnv.y, pnv.z, pnv.w};
            uint32_t u[4];
#pragma unroll
            for (int t = 0; t < 4; t++) {
                int k = q*4 + t;
                float phe = beL[k];
#pragma unroll
                for (int h = 0; h < 8; h++) phe = fmaf(h8[h], WEs[h*64 + k0 + k], phe);
                u[t] = to_tf32(pc[k] * pn[t] * phe);
            }
            *(uint4*)(As + p*KC_SA + k0 + q*4) = make_uint4(u[0], u[1], u[2], u[3]);
        }
    }
    __syncthreads();

    // ---- tensor-core GEMM ----
    int w = tid >> 5, lane = tid & 31;
    int aatom = w >> 2, g = w & 3;
    int lg = lane >> 2, lt = lane & 3;
    // base pointers: all loop offsets become compile-time constants
    const uint32_t* pA = (const uint32_t*)As + (aatom*32 + lg)*KC_SA + lt;
    const uint32_t* pB = (const uint32_t*)Bs + lt*KC_SB + g*16 + lg;

    float Cg[2][2][4], Cm[2][2][4];   // [m-tile][n-tile][frag]
#pragma unroll
    for (int mt = 0; mt < 2; mt++)
#pragma unroll
        for (int nt = 0; nt < 2; nt++)
#pragma unroll
            for (int q = 0; q < 4; q++) { Cg[mt][nt][q] = 0.0f; Cm[mt][nt][q] = 0.0f; }

#pragma unroll
    for (int kt = 0; kt < 8; kt++) {
        uint32_t a[2][4];
#pragma unroll
        for (int mt = 0; mt < 2; mt++) {
            const uint32_t* pr = pA + mt*16*KC_SA + kt*8;
            a[mt][0] = pr[0];
            a[mt][1] = pr[8*KC_SA];
            a[mt][2] = pr[4];
            a[mt][3] = pr[8*KC_SA + 4];
        }
#pragma unroll
        for (int nt = 0; nt < 2; nt++) {
            const uint32_t* pb = pB + kt*8*KC_SB + nt*8;
            uint32_t bgf[2] = { pb[0],  pb[4*KC_SB] };
            uint32_t bmf[2] = { pb[64], pb[4*KC_SB + 64] };
            mma8(Cg[0][nt], a[0], bgf);
            mma8(Cg[1][nt], a[1], bgf);
            mma8(Cm[0][nt], a[0], bmf);
            mma8(Cm[1][nt], a[1], bmf);
        }
    }

    // ---- epilogue: sigmoid(gate)*softplus(mag), sum over 32 rows of the atom ----
    float s[2][2];
    s[0][0] = 0.0f; s[0][1] = 0.0f; s[1][0] = 0.0f; s[1][1] = 0.0f;
#pragma unroll
    for (int mt = 0; mt < 2; mt++) {
#pragma unroll
        for (int nt = 0; nt < 2; nt++) {
            int cb = g*16 + nt*8 + 2*lt;
#pragma unroll
            for (int j = 0; j < 4; j++) {
                int col = cb + (j & 1);
                float gv = sigm(Cg[mt][nt][j] + BGs[col]);
                float mv = sftp(Cm[mt][nt][j] + BMs[col]);
                s[nt][j & 1] = fmaf(gv, mv, s[nt][j & 1]);
            }
        }
    }
#pragma unroll
    for (int o = 4; o <= 16; o <<= 1) {
        s[0][0] += __shfl_xor_sync(0xffffffffu, s[0][0], o);
        s[0][1] += __shfl_xor_sync(0xffffffffu, s[0][1], o);
        s[1][0] += __shfl_xor_sync(0xffffffffu, s[1][0], o);
        s[1][1] += __shfl_xor_sync(0xffffffffu, s[1][1], o);
    }
    if (lane < 4) {
#pragma unroll
        for (int nt = 0; nt < 2; nt++) {
#pragma unroll
            for (int q = 0; q < 2; q++) {
                int col = g*16 + nt*8 + 2*lane + q;
                g_atom[bi*256 + aatom*64 + col] += s[nt][q];
            }
        }
    }
}

// ---------------- 5) readout stage 1 ----------------
__global__ void k_read1(const float* __restrict__ W, const float* __restrict__ b) {
    __shared__ float Ws[FF*HH];
    __shared__ float bs[HH];
    __shared__ float xb[8][FF];
    int tid = threadIdx.x;
    for (int i = tid; i < FF*HH; i += 256) Ws[i] = W[i];
    if (tid < HH) bs[tid] = b[tid];
    int w = tid >> 5, l = tid & 31;
    int i = blockIdx.x * 8 + w;
    xb[w][l] = g_atom[i*FF + l];  xb[w][l+32] = g_atom[i*FF + l + 32];
    __syncthreads();
    float acc[4];
#pragma unroll
    for (int m = 0; m < 4; m++) acc[m] = bs[l + 32*m];
#pragma unroll 4
    for (int k = 0; k < FF; k++) {
        float x = xb[w][k];
#pragma unroll
        for (int m = 0; m < 4; m++) acc[m] = fmaf(x, Ws[k*HH + l + 32*m], acc[m]);
    }
#pragma unroll
    for (int m = 0; m < 4; m++) g_h1[i*HH + l + 32*m] = sftp(acc[m]);
}

// ---------------- 6) readout stage 2 ----------------
__global__ void k_read2(const float* __restrict__ W2, const float* __restrict__ b2,
                        const float* __restrict__ W3, const float* __restrict__ b3) {
    __shared__ float Ws[HH*FF];
    __shared__ float b2s[FF];
    __shared__ float w3s[FF];
    __shared__ float hb[8][HH];
    int tid = threadIdx.x;
    for (int i = tid; i < HH*FF; i += 256) Ws[i] = W2[i];
    if (tid < FF) { b2s[tid] = b2[tid]; w3s[tid] = W3[tid]; }
    int w = tid >> 5, l = tid & 31;
    int i = blockIdx.x * 8 + w;
#pragma unroll
    for (int m = 0; m < 4; m++) hb[w][l + 32*m] = g_h1[i*HH + l + 32*m];
    __syncthreads();
    float a0 = b2s[l], a1 = b2s[l+32];
#pragma unroll 4
    for (int k = 0; k < HH; k++) {
        float x = hb[w][k];
        a0 = fmaf(x, Ws[k*FF + l],      a0);
        a1 = fmaf(x, Ws[k*FF + l + 32], a1);
    }
    float e = sftp(a0) * w3s[l] + sftp(a1) * w3s[l+32];
    e = wsum(e);
    if (l == 0) g_esite[i] = e + b3[0];
}

// ---------------- 7) p_i / p_j ----------------
__global__ void k_pij(const float* __restrict__ Wj1) {
    __shared__ float Ws[FF*32];
    __shared__ float xb[8][FF];
    int tid = threadIdx.x;
    for (int i = tid; i < FF*32; i += 256) {
        int k = i >> 5, c = i & 31;
        Ws[i] = (c < 16) ? Wj1[k*16 + c] : Wj1[(64 + k)*16 + (c - 16)];
    }
    int w = tid >> 5, l = tid & 31;
    int i = blockIdx.x * 8 + w;
    xb[w][l] = g_atom[i*FF + l];  xb[w][l+32] = g_atom[i*FF + l + 32];
    __syncthreads();
    float acc = 0.0f;
#pragma unroll 4
    for (int k = 0; k < FF; k++) acc = fmaf(xb[w][k], Ws[k*32 + l], acc);
    if (l < 16) g_pi[i*16 + l] = acc;
    else        g_pj[i*16 + (l - 16)] = acc;
}

// ---------------- 8) E_mag ----------------
__global__ void k_emag(const int* __restrict__ nbr_idx, const float* __restrict__ spins,
                       const float* __restrict__ Wj1, const float* __restrict__ bj1,
                       const float* __restrict__ Wj2, const float* __restrict__ bj2) {
    __shared__ float Wne[8*16];
    __shared__ float w2s[16];
    __shared__ float b1s[16];
    __shared__ float pib[8][16];
    int tid = threadIdx.x;
    if (tid < 128) Wne[tid] = Wj1[128*16 + tid];
    if (tid < 16) { w2s[tid] = Wj2[tid]; b1s[tid] = bj1[tid]; }
    int w = tid >> 5, j = tid & 31;
    int i = blockIdx.x * 8 + w;
    if (j < 16) pib[w][j] = g_pi[i*16 + j];
    __syncthreads();
    int nid = nbr_idx[i*MM + j];
    const float4* pj4 = (const float4*)(g_pj + nid*16);
    float4 p0 = pj4[0], p1 = pj4[1], p2 = pj4[2], p3 = pj4[3];
    float pj[16] = {p0.x,p0.y,p0.z,p0.w, p1.x,p1.y,p1.z,p1.w,
                    p2.x,p2.y,p2.z,p2.w, p3.x,p3.y,p3.z,p3.w};
    const float4* h4 = (const float4*)(g_nbrh + (i*MM + j)*8);
    float4 hA = h4[0], hB = h4[1];
    float h8[8] = {hA.x,hA.y,hA.z,hA.w, hB.x,hB.y,hB.z,hB.w};
    float J = bj2[0];
#pragma unroll
    for (int c = 0; c < 16; c++) {
        float q = pib[w][c] + pj[c] + b1s[c];
#pragma unroll
        for (int h = 0; h < 8; h++) q = fmaf(h8[h], Wne[h*16 + c], q);
        J = fmaf(sftp(q), w2s[c], J);
    }
    float contrib = J * spins[i] * spins[nid] * g_mask[i*MM + j];
    contrib = wsum(contrib);
    if (j == 0) g_esite[i] += contrib;
}

// ---------------- 9) deterministic final reduction ----------------
__global__ void k_reduce(float* __restrict__ out) {
    __shared__ float sb[1024];
    int t = threadIdx.x;
    float s = 0.0f;
    for (int i = t; i < NA; i += 1024) s += g_esite[i];
    sb[t] = s;
    __syncthreads();
    for (int o = 512; o; o >>= 1) {
        if (t < o) sb[t] += sb[t + o];
        __syncthreads();
    }
    if (t == 0) out[0] = sb[0];
}

// ---------------- host launcher ----------------
extern "C" void kernel_launch(void* const* d_in, const int* in_sizes, int n_in,
                              void* d_out, int out_size) {
    const float* atom_fea = (const float*)d_in[0];
    const float* nbr_fea  = (const float*)d_in[1];
    const int*   nbr_idx  = (const int*)  d_in[2];
    const float* spins    = (const float*)d_in[3];
    const float* W_embed  = (const float*)d_in[4];
    const float* b_embed  = (const float*)d_in[5];
    const float* W_nbrh   = (const float*)d_in[6];
    const float* b_nbrh   = (const float*)d_in[7];
    const float* ln_s     = (const float*)d_in[8];
    const float* ln_b     = (const float*)d_in[9];
    const float* Wc       = (const float*)d_in[10];
    const float* bc       = (const float*)d_in[11];
    const float* Wn       = (const float*)d_in[12];
    const float* bn       = (const float*)d_in[13];
    const float* We       = (const float*)d_in[14];
    const float* be       = (const float*)d_in[15];
    const float* Wg       = (const float*)d_in[16];
    const float* bg       = (const float*)d_in[17];
    const float* Wm       = (const float*)d_in[18];
    const float* bm       = (const float*)d_in[19];
    const float* Wr1      = (const float*)d_in[20];
    const float* br1      = (const float*)d_in[21];
    const float* Wr2      = (const float*)d_in[22];
    const float* br2      = (const float*)d_in[23];
    const float* Wr3      = (const float*)d_in[24];
    const float* br3      = (const float*)d_in[25];
    const float* Wj1      = (const float*)d_in[26];
    const float* bj1      = (const float*)d_in[27];
    const float* Wj2      = (const float*)d_in[28];
    const float* bj2      = (const float*)d_in[29];

    static bool s_attr_done = false;
    if (!s_attr_done) {
        cudaFuncSetAttribute(k_conv, cudaFuncAttributeMaxDynamicSharedMemorySize,
                             KC_FLOATS * (int)sizeof(float));
        s_attr_done = true;
    }

    k_embed<<<NA/8, 256>>>(atom_fea, W_embed, b_embed);
    k_nbrh <<<NA*MM/256, 256>>>((const float4*)nbr_fea, W_nbrh, b_nbrh);
    for (int L = 0; L < 2; L++) {
        k_lnphi<<<NA/8, 256>>>(ln_s + L*FF, ln_b + L*FF,
                               Wc + L*FF*FF, bc + L*FF,
                               Wn + L*FF*FF, bn + L*FF);
        k_conv<<<NA/4, 512, KC_FLOATS * sizeof(float)>>>(
            Wg + L*FF*FF, bg + L*FF,
            Wm + L*FF*FF, bm + L*FF,
            We + L*NBH*FF, be + L*FF, nbr_idx);
    }
    k_read1<<<NA/8, 256>>>(Wr1, br1);
    k_read2<<<NA/8, 256>>>(Wr2, br2, Wr3, br3);
    k_pij  <<<NA/8, 256>>>(Wj1);
    k_emag <<<NA/8, 256>>>(nbr_idx, spins, Wj1, bj1, Wj2, bj2);
    k_reduce<<<1, 1024>>>((float*)d_out);
}

// round 15
// speedup vs baseline: 1.2605x; 1.2605x over previous
#include <cuda_runtime.h>
#include <cstdint>

#define NA  32768
#define MM  32
#define AIN 92
#define FF  64
#define NBH 8
#define HH  128
#define ODD 16

// ---------------- scratch (static device globals; no allocation) ----------------
__device__ float g_atom [NA*FF];
__device__ float g_nbrh [NA*MM*NBH];
__device__ float g_mask [NA*MM];
__device__ float g_phic [NA*FF];
__device__ float g_phin [NA*FF];
__device__ float g_h1   [NA*HH];
__device__ float g_pi   [NA*ODD];
__device__ float g_pj   [NA*ODD];
__device__ float g_esite[NA];

// ---------------- helpers ----------------
__device__ __forceinline__ float wsum(float v) {
#pragma unroll
    for (int o = 16; o; o >>= 1) v += __shfl_xor_sync(0xffffffffu, v, o);
    return v;
}
__device__ __forceinline__ float sigm(float x) {
    return __fdividef(1.0f, 1.0f + __expf(-x));
}
__device__ __forceinline__ float sftp(float x) {
    return (x > 15.0f) ? x : __logf(1.0f + __expf(x));
}
__device__ __forceinline__ uint32_t to_tf32(float x) {
    uint32_t r;
    asm("cvt.rna.tf32.f32 %0, %1;" : "=r"(r) : "f"(x));
    return r;
}
__device__ __forceinline__ uint32_t smem_u32(const void* p) {
    uint32_t a;
    asm("{ .reg .u64 t; cvta.to.shared.u64 t, %1; cvt.u32.u64 %0, t; }" : "=r"(a) : "l"(p));
    return a;
}
// m16n8k8 tf32 mma, fp32 accumulate
__device__ __forceinline__ void mma8(float* c, const uint32_t* a, const uint32_t* b) {
    asm volatile("mma.sync.aligned.m16n8k8.row.col.f32.tf32.tf32.f32 "
        "{%0,%1,%2,%3}, {%4,%5,%6,%7}, {%8,%9}, {%0,%1,%2,%3};"
        : "+f"(c[0]), "+f"(c[1]), "+f"(c[2]), "+f"(c[3])
        : "r"(a[0]), "r"(a[1]), "r"(a[2]), "r"(a[3]), "r"(b[0]), "r"(b[1]));
}

// SMEM float offsets for k_conv
#define KC_SA   68              // A row stride (floats)
#define KC_AOF  0               // A: 128*68 = 8704 floats
#define KC_BOF  8704            // Bp: 32 rows * 66 float4 = 8448 floats
#define KC_WE   17152           // WET[k][h]: 512 floats
#define KC_BE   17664           // 64
#define KC_BG   17728           // 64
#define KC_BM   17792           // 64
#define KC_PC   17856           // 256
#define KC_FLOATS 18112         // 72448 bytes

// ---------------- 1) embed: 16 atoms / 512 threads ----------------
__global__ void k_embed(const float* __restrict__ atom_fea,
                        const float* __restrict__ W, const float* __restrict__ b) {
    __shared__ float Ws[AIN*FF];
    __shared__ float bs[FF];
    __shared__ float xb[16][AIN + 1];
    int tid = threadIdx.x;
    for (int i = tid; i < AIN*FF; i += 512) Ws[i] = W[i];
    if (tid < FF) bs[tid] = b[tid];
    int w = tid >> 5, l = tid & 31;
    int i = blockIdx.x * 16 + w;
    for (int k = l; k < AIN; k += 32) xb[w][k] = atom_fea[i*AIN + k];
    __syncthreads();
    float a0 = bs[l], a1 = bs[l+32];
#pragma unroll 4
    for (int k = 0; k < AIN; k++) {
        float x = xb[w][k];
        a0 = fmaf(x, Ws[k*FF + l],      a0);
        a1 = fmaf(x, Ws[k*FF + l + 32], a1);
    }
    g_atom[i*FF + l]      = a0;
    g_atom[i*FF + l + 32] = a1;
}

// ---------------- 2) nbr_h + mask ----------------
__global__ void k_nbrh(const float4* __restrict__ nbr_fea4,
                       const float* __restrict__ W, const float* __restrict__ b) {
    __shared__ float Ws[64];
    __shared__ float bs[8];
    int tid = threadIdx.x;
    if (tid < 64) Ws[tid] = W[tid];
    if (tid < 8)  bs[tid] = b[tid];
    __syncthreads();
    int p = blockIdx.x * 256 + tid;
    float4 x0 = nbr_fea4[p*2], x1 = nbr_fea4[p*2 + 1];
    float x[8] = {x0.x, x0.y, x0.z, x0.w, x1.x, x1.y, x1.z, x1.w};
    float mk = 0.0f;
#pragma unroll
    for (int h = 0; h < 8; h++) if (x[h] > 0.0f) mk = 1.0f;
    float o[8];
#pragma unroll
    for (int c = 0; c < 8; c++) {
        float acc = bs[c];
#pragma unroll
        for (int h = 0; h < 8; h++) acc = fmaf(x[h], Ws[h*8 + c], acc);
        o[c] = acc;
    }
    float4* out4 = (float4*)(g_nbrh + p*8);
    out4[0] = make_float4(o[0], o[1], o[2], o[3]);
    out4[1] = make_float4(o[4], o[5], o[6], o[7]);
    g_mask[p] = mk;
}

// ---------------- 3) LN + phi_c/phi_n: 16 atoms / 512 threads ----------------
__global__ void k_lnphi(const float* __restrict__ ln_s, const float* __restrict__ ln_b,
                        const float* __restrict__ Wc, const float* __restrict__ bc,
                        const float* __restrict__ Wn, const float* __restrict__ bn) {
    __shared__ float Wcs[FF*FF];
    __shared__ float Wns[FF*FF];
    __shared__ float bcs[FF], bns[FF], lss[FF], lbs[FF];
    __shared__ float nb[16][FF];
    int tid = threadIdx.x;
    for (int i = tid; i < FF*FF; i += 512) { Wcs[i] = Wc[i]; Wns[i] = Wn[i]; }
    if (tid < FF) { bcs[tid] = bc[tid]; bns[tid] = bn[tid]; lss[tid] = ln_s[tid]; lbs[tid] = ln_b[tid]; }
    int w = tid >> 5, l = tid & 31;
    int i = blockIdx.x * 16 + w;
    float x0 = g_atom[i*FF + l], x1 = g_atom[i*FF + l + 32];
    float mu = wsum(x0 + x1) * (1.0f / 64.0f);
    float d0 = x0 - mu, d1 = x1 - mu;
    float var = wsum(d0*d0 + d1*d1) * (1.0f / 64.0f);
    float rstd = rsqrtf(var + 1e-6f);
    __syncthreads();
    nb[w][l]      = fmaf(d0 * rstd, lss[l],      lbs[l]);
    nb[w][l + 32] = fmaf(d1 * rstd, lss[l + 32], lbs[l + 32]);
    __syncwarp();
    float c0 = bcs[l], c1 = bcs[l+32], n0 = bns[l], n1 = bns[l+32];
#pragma unroll 4
    for (int k = 0; k < FF; k++) {
        float nv = nb[w][k];
        c0 = fmaf(nv, Wcs[k*FF + l],      c0);
        c1 = fmaf(nv, Wcs[k*FF + l + 32], c1);
        n0 = fmaf(nv, Wns[k*FF + l],      n0);
        n1 = fmaf(nv, Wns[k*FF + l + 32], n1);
    }
    g_phic[i*FF + l] = c0;  g_phic[i*FF + l + 32] = c1;
    g_phin[i*FF + l] = n0;  g_phin[i*FF + l + 32] = n1;
}

// ---------------- 4) fused conv: mma.sync tf32, 512 threads ----------------
// block = 4 atoms = 128 pairs. D[128p x 128c] = A[128p x 64k] @ B[64k x 128c]
// Bp rows j = kt*4+lt hold {G(k,n),G(k+4,n),M(k,n),M(k+4,n)} per n (stride 66 float4).
__global__ void __launch_bounds__(512, 2)
k_conv(const float* __restrict__ Wg, const float* __restrict__ bg,
       const float* __restrict__ Wm, const float* __restrict__ bm,
       const float* __restrict__ We, const float* __restrict__ be,
       const int* __restrict__ nbr_idx) {
    extern __shared__ float sm[];
    float* As  = sm + KC_AOF;
    uint4* Bp4 = (uint4*)(sm + KC_BOF);
    float* WETs= sm + KC_WE;
    float* BEs = sm + KC_BE;
    float* BGs = sm + KC_BG;
    float* BMs = sm + KC_BM;
    float* PCs = sm + KC_PC;

    int tid = threadIdx.x, bi = blockIdx.x;

    // ---- early: async gather of phi_n quarters directly into A slots ----
    int p = tid & 127, quarter = tid >> 7, a = p >> 5;
    int gp = bi*128 + p;
    int nidx = nbr_idx[gp];
    int k0 = quarter * 16;
    {
        uint32_t dst = smem_u32(As + p*KC_SA + k0);
        const char* src = (const char*)(g_phin + nidx*64 + k0);
#pragma unroll
        for (int q = 0; q < 4; q++) {
            asm volatile("cp.async.cg.shared.global [%0], [%1], 16;"
                         :: "r"(dst + q*16), "l"(src + q*16) : "memory");
        }
        asm volatile("cp.async.commit_group;" ::: "memory");
    }
    // nbr hidden for this pair (registers)
    const float4* h4 = (const float4*)(g_nbrh + gp*8);
    float4 hA = h4[0], hB = h4[1];
    float h8[8] = {hA.x, hA.y, hA.z, hA.w, hB.x, hB.y, hB.z, hB.w};

    // ---- stage Bp (packed tf32 quads), WET (transposed We), biases, phi_c ----
    for (int idx = tid; idx < 2048; idx += 512) {
        int j = idx >> 6, n = idx & 63;
        int k = (j >> 2)*8 + (j & 3);
        Bp4[j*66 + n] = make_uint4(to_tf32(Wg[k*64 + n]),       to_tf32(Wg[(k+4)*64 + n]),
                                   to_tf32(Wm[k*64 + n]),       to_tf32(Wm[(k+4)*64 + n]));
    }
    WETs[tid] = We[(tid & 7)*64 + (tid >> 3)];     // WET[k][h] = We[h][k]
    if (tid < 64) { BEs[tid] = be[tid]; BGs[tid] = bg[tid]; BMs[tid] = bm[tid]; }
    if (tid < 256) PCs[tid] = g_phic[bi*256 + tid];
    __syncthreads();

    // ---- in-place multiply: A = phi_c * phi_n * phi_e (tf32) ----
    asm volatile("cp.async.wait_group 0;" ::: "memory");
    {
        const float* pc  = PCs + a*64 + k0;
        const float* beL = BEs + k0;
        uint4* arow = (uint4*)(As + p*KC_SA + k0);
#pragma unroll
        for (int q = 0; q < 4; q++) {
            uint4 pv = arow[q];
            float pn[4] = {__uint_as_float(pv.x), __uint_as_float(pv.y),
                           __uint_as_float(pv.z), __uint_as_float(pv.w)};
            uint32_t u[4];
#pragma unroll
            for (int t = 0; t < 4; t++) {
                int k = k0 + q*4 + t;
                const float4* wt = (const float4*)(WETs) + k*2;
                float4 w0 = wt[0], w1 = wt[1];
                float phe = beL[q*4 + t];
                phe = fmaf(h8[0], w0.x, phe); phe = fmaf(h8[1], w0.y, phe);
                phe = fmaf(h8[2], w0.z, phe); phe = fmaf(h8[3], w0.w, phe);
                phe = fmaf(h8[4], w1.x, phe); phe = fmaf(h8[5], w1.y, phe);
                phe = fmaf(h8[6], w1.z, phe); phe = fmaf(h8[7], w1.w, phe);
                u[t] = to_tf32(pc[q*4 + t] * pn[t] * phe);
            }
            arow[q] = make_uint4(u[0], u[1], u[2], u[3]);
        }
    }
    __syncthreads();

    // ---- tensor-core GEMM: warp = (atom = w>>2, col-quarter g = w&3) ----
    int w = tid >> 5, lane = tid & 31;
    int aatom = w >> 2, g = w & 3;
    int lg = lane >> 2, lt = lane & 3;
    const uint32_t* pA = (const uint32_t*)As + (aatom*32 + lg)*KC_SA + lt;
    const uint4*    pB = Bp4 + lt*66 + g*16 + lg;

    float Cg[2][2][4], Cm[2][2][4];
#pragma unroll
    for (int mt = 0; mt < 2; mt++)
#pragma unroll
        for (int nt = 0; nt < 2; nt++)
#pragma unroll
            for (int q = 0; q < 4; q++) { Cg[mt][nt][q] = 0.0f; Cm[mt][nt][q] = 0.0f; }

#pragma unroll
    for (int kt = 0; kt < 8; kt++) {
        uint32_t afr[2][4];
#pragma unroll
        for (int mt = 0; mt < 2; mt++) {
            const uint32_t* pr = pA + mt*16*KC_SA + kt*8;
            afr[mt][0] = pr[0];
            afr[mt][1] = pr[8*KC_SA];
            afr[mt][2] = pr[4];
            afr[mt][3] = pr[8*KC_SA + 4];
        }
#pragma unroll
        for (int nt = 0; nt < 2; nt++) {
            uint4 v = pB[kt*264 + nt*8];
            uint32_t bgf[2] = { v.x, v.y };
            uint32_t bmf[2] = { v.z, v.w };
            mma8(Cg[0][nt], afr[0], bgf);
            mma8(Cg[1][nt], afr[1], bgf);
            mma8(Cm[0][nt], afr[0], bmf);
            mma8(Cm[1][nt], afr[1], bmf);
        }
    }

    // ---- epilogue ----
    float s[2][2];
    s[0][0] = 0.0f; s[0][1] = 0.0f; s[1][0] = 0.0f; s[1][1] = 0.0f;
#pragma unroll
    for (int mt = 0; mt < 2; mt++) {
#pragma unroll
        for (int nt = 0; nt < 2; nt++) {
            int cb = g*16 + nt*8 + 2*lt;
#pragma unroll
            for (int j = 0; j < 4; j++) {
                int col = cb + (j & 1);
                float gv = sigm(Cg[mt][nt][j] + BGs[col]);
                float mv = sftp(Cm[mt][nt][j] + BMs[col]);
                s[nt][j & 1] = fmaf(gv, mv, s[nt][j & 1]);
            }
        }
    }
#pragma unroll
    for (int o = 4; o <= 16; o <<= 1) {
        s[0][0] += __shfl_xor_sync(0xffffffffu, s[0][0], o);
        s[0][1] += __shfl_xor_sync(0xffffffffu, s[0][1], o);
        s[1][0] += __shfl_xor_sync(0xffffffffu, s[1][0], o);
        s[1][1] += __shfl_xor_sync(0xffffffffu, s[1][1], o);
    }
    if (lane < 4) {
#pragma unroll
        for (int nt = 0; nt < 2; nt++) {
#pragma unroll
            for (int q = 0; q < 2; q++) {
                int col = g*16 + nt*8 + 2*lane + q;
                g_atom[bi*256 + aatom*64 + col] += s[nt][q];
            }
        }
    }
}

// ---------------- 5) readout stage 1: 16 atoms / 512 threads ----------------
__global__ void k_read1(const float* __restrict__ W, const float* __restrict__ b) {
    __shared__ float Ws[FF*HH];
    __shared__ float bs[HH];
    __shared__ float xb[16][FF];
    int tid = threadIdx.x;
    for (int i = tid; i < FF*HH; i += 512) Ws[i] = W[i];
    if (tid < HH) bs[tid] = b[tid];
    int w = tid >> 5, l = tid & 31;
    int i = blockIdx.x * 16 + w;
    xb[w][l] = g_atom[i*FF + l];  xb[w][l+32] = g_atom[i*FF + l + 32];
    __syncthreads();
    float acc[4];
#pragma unroll
    for (int m = 0; m < 4; m++) acc[m] = bs[l + 32*m];
#pragma unroll 4
    for (int k = 0; k < FF; k++) {
        float x = xb[w][k];
#pragma unroll
        for (int m = 0; m < 4; m++) acc[m] = fmaf(x, Ws[k*HH + l + 32*m], acc[m]);
    }
#pragma unroll
    for (int m = 0; m < 4; m++) g_h1[i*HH + l + 32*m] = sftp(acc[m]);
}

// ---------------- 6) readout stage 2: 16 atoms / 512 threads ----------------
__global__ void k_read2(const float* __restrict__ W2, const float* __restrict__ b2,
                        const float* __restrict__ W3, const float* __restrict__ b3) {
    __shared__ float Ws[HH*FF];
    __shared__ float b2s[FF];
    __shared__ float w3s[FF];
    __shared__ float hb[16][HH];
    int tid = threadIdx.x;
    for (int i = tid; i < HH*FF; i += 512) Ws[i] = W2[i];
    if (tid < FF) { b2s[tid] = b2[tid]; w3s[tid] = W3[tid]; }
    int w = tid >> 5, l = tid & 31;
    int i = blockIdx.x * 16 + w;
#pragma unroll
    for (int m = 0; m < 4; m++) hb[w][l + 32*m] = g_h1[i*HH + l + 32*m];
    __syncthreads();
    float a0 = b2s[l], a1 = b2s[l+32];
#pragma unroll 4
    for (int k = 0; k < HH; k++) {
        float x = hb[w][k];
        a0 = fmaf(x, Ws[k*FF + l],      a0);
        a1 = fmaf(x, Ws[k*FF + l + 32], a1);
    }
    float e = sftp(a0) * w3s[l] + sftp(a1) * w3s[l+32];
    e = wsum(e);
    if (l == 0) g_esite[i] = e + b3[0];
}

// ---------------- 7) p_i / p_j: 16 atoms / 512 threads ----------------
__global__ void k_pij(const float* __restrict__ Wj1) {
    __shared__ float Ws[FF*32];
    __shared__ float xb[16][FF];
    int tid = threadIdx.x;
    for (int i = tid; i < FF*32; i += 512) {
        int k = i >> 5, c = i & 31;
        Ws[i] = (c < 16) ? Wj1[k*16 + c] : Wj1[(64 + k)*16 + (c - 16)];
    }
    int w = tid >> 5, l = tid & 31;
    int i = blockIdx.x * 16 + w;
    xb[w][l] = g_atom[i*FF + l];  xb[w][l+32] = g_atom[i*FF + l + 32];
    __syncthreads();
    float acc = 0.0f;
#pragma unroll 4
    for (int k = 0; k < FF; k++) acc = fmaf(xb[w][k], Ws[k*32 + l], acc);
    if (l < 16) g_pi[i*16 + l] = acc;
    else        g_pj[i*16 + (l - 16)] = acc;
}

// ---------------- 8) E_mag ----------------
__global__ void k_emag(const int* __restrict__ nbr_idx, const float* __restrict__ spins,
                       const float* __restrict__ Wj1, const float* __restrict__ bj1,
                       const float* __restrict__ Wj2, const float* __restrict__ bj2) {
    __shared__ float Wne[8*16];
    __shared__ float w2s[16];
    __shared__ float b1s[16];
    __shared__ float pib[8][16];
    int tid = threadIdx.x;
    if (tid < 128) Wne[tid] = Wj1[128*16 + tid];
    if (tid < 16) { w2s[tid] = Wj2[tid]; b1s[tid] = bj1[tid]; }
    int w = tid >> 5, j = tid & 31;
    int i = blockIdx.x * 8 + w;
    if (j < 16) pib[w][j] = g_pi[i*16 + j];
    __syncthreads();
    int nid = nbr_idx[i*MM + j];
    const float4* pj4 = (const float4*)(g_pj + nid*16);
    float4 p0 = pj4[0], p1 = pj4[1], p2 = pj4[2], p3 = pj4[3];
    float pj[16] = {p0.x,p0.y,p0.z,p0.w, p1.x,p1.y,p1.z,p1.w,
                    p2.x,p2.y,p2.z,p2.w, p3.x,p3.y,p3.z,p3.w};
    const float4* h4 = (const float4*)(g_nbrh + (i*MM + j)*8);
    float4 hA = h4[0], hB = h4[1];
    float h8[8] = {hA.x,hA.y,hA.z,hA.w, hB.x,hB.y,hB.z,hB.w};
    float J = bj2[0];
#pragma unroll
    for (int c = 0; c < 16; c++) {
        float q = pib[w][c] + pj[c] + b1s[c];
#pragma unroll
        for (int h = 0; h < 8; h++) q = fmaf(h8[h], Wne[h*16 + c], q);
        J = fmaf(sftp(q), w2s[c], J);
    }
    float contrib = J * spins[i] * spins[nid] * g_mask[i*MM + j];
    contrib = wsum(contrib);
    if (j == 0) g_esite[i] += contrib;
}

// ---------------- 9) deterministic final reduction ----------------
__global__ void k_reduce(float* __restrict__ out) {
    __shared__ float sb[1024];
    int t = threadIdx.x;
    float s = 0.0f;
    for (int i = t; i < NA; i += 1024) s += g_esite[i];
    sb[t] = s;
    __syncthreads();
    for (int o = 512; o; o >>= 1) {
        if (t < o) sb[t] += sb[t + o];
        __syncthreads();
    }
    if (t == 0) out[0] = sb[0];
}

// ---------------- host launcher ----------------
extern "C" void kernel_launch(void* const* d_in, const int* in_sizes, int n_in,
                              void* d_out, int out_size) {
    const float* atom_fea = (const float*)d_in[0];
    const float* nbr_fea  = (const float*)d_in[1];
    const int*   nbr_idx  = (const int*)  d_in[2];
    const float* spins    = (const float*)d_in[3];
    const float* W_embed  = (const float*)d_in[4];
    const float* b_embed  = (const float*)d_in[5];
    const float* W_nbrh   = (const float*)d_in[6];
    const float* b_nbrh   = (const float*)d_in[7];
    const float* ln_s     = (const float*)d_in[8];
    const float* ln_b     = (const float*)d_in[9];
    const float* Wc       = (const float*)d_in[10];
    const float* bc       = (const float*)d_in[11];
    const float* Wn       = (const float*)d_in[12];
    const float* bn       = (const float*)d_in[13];
    const float* We       = (const float*)d_in[14];
    const float* be       = (const float*)d_in[15];
    const float* Wg       = (const float*)d_in[16];
    const float* bg       = (const float*)d_in[17];
    const float* Wm       = (const float*)d_in[18];
    const float* bm       = (const float*)d_in[19];
    const float* Wr1      = (const float*)d_in[20];
    const float* br1      = (const float*)d_in[21];
    const float* Wr2      = (const float*)d_in[22];
    const float* br2      = (const float*)d_in[23];
    const float* Wr3      = (const float*)d_in[24];
    const float* br3      = (const float*)d_in[25];
    const float* Wj1      = (const float*)d_in[26];
    const float* bj1      = (const float*)d_in[27];
    const float* Wj2      = (const float*)d_in[28];
    const float* bj2      = (const float*)d_in[29];

    static bool s_attr_done = false;
    if (!s_attr_done) {
        cudaFuncSetAttribute(k_conv, cudaFuncAttributeMaxDynamicSharedMemorySize,
                             KC_FLOATS * (int)sizeof(float));
        s_attr_done = true;
    }

    k_embed<<<NA/16, 512>>>(atom_fea, W_embed, b_embed);
    k_nbrh <<<NA*MM/256, 256>>>((const float4*)nbr_fea, W_nbrh, b_nbrh);
    for (int L = 0; L < 2; L++) {
        k_lnphi<<<NA/16, 512>>>(ln_s + L*FF, ln_b + L*FF,
                                Wc + L*FF*FF, bc + L*FF,
                                Wn + L*FF*FF, bn + L*FF);
        k_conv<<<NA/4, 512, KC_FLOATS * sizeof(float)>>>(
            Wg + L*FF*FF, bg + L*FF,
            Wm + L*FF*FF, bm + L*FF,
            We + L*NBH*FF, be + L*FF, nbr_idx);
    }
    k_read1<<<NA/16, 512>>>(Wr1, br1);
    k_read2<<<NA/16, 512>>>(Wr2, br2, Wr3, br3);
    k_pij  <<<NA/16, 512>>>(Wj1);
    k_emag <<<NA/8, 256>>>(nbr_idx, spins, Wj1, bj1, Wj2, bj2);
    k_reduce<<<1, 1024>>>((float*)d_out);
}